// round 15
// baseline (speedup 1.0000x reference)
#include <cuda_runtime.h>
#include <cuda_bf16.h>
#include <math.h>
#include <stdint.h>

// ---------------- problem constants ----------------
#define BBATCH 64
#define SSEQ   256
#define HHID   256
#define MROWS  16384
#define BTROWS 16384

// ---------------- fp32 scratch ----------------
#define O_XGF   ((size_t)0)
#define SZ_XG   ((size_t)MROWS*1024)
#define O_XGB   (O_XGF+SZ_XG)
#define O_HID   (O_XGB+SZ_XG)
#define SZ_HID  ((size_t)BTROWS*512)
#define O_RHID  (O_HID+SZ_HID)
#define O_WHHT  (O_RHID+SZ_HID)
#define SZ_WHHT ((size_t)HHID*HHID*4)
#define O_HTF   (O_WHHT+4*SZ_WHHT)
#define SZ_HT   ((size_t)2*HHID*BBATCH)
#define O_HTB   (O_HTF+SZ_HT)
#define O_OWT   (O_HTB+SZ_HT)
#define SZ_OWT  ((size_t)512*96)
#define O_BS1   (O_OWT+SZ_OWT)
#define O_BS2   (O_BS1+2048)
#define O_BSM   (O_BS2+2048)
#define F32_TOTAL (O_BSM+1024)

__device__ float g_f32[F32_TOTAL];

// ---------------- bf16 scratch ----------------
#define B_IVHI ((size_t)0)
#define SZ_IV  ((size_t)MROWS*192)
#define B_IVLO (B_IVHI+SZ_IV)
#define B_AVHI (B_IVLO+SZ_IV)
#define SZ_AV  ((size_t)MROWS*512)
#define B_AVLO (B_AVHI+SZ_AV)
#define B_V2HI (B_AVLO+SZ_AV)
#define B_V2LO (B_V2HI+SZ_AV)
#define B_W1HI (B_V2LO+SZ_AV)
#define SZ_W1  ((size_t)2048*192)
#define B_W1LO (B_W1HI+SZ_W1)
#define B_W2HI (B_W1LO+SZ_W1)
#define SZ_W2  ((size_t)2048*512)
#define B_W2LO (B_W2HI+SZ_W2)
#define B_WMHI (B_W2LO+SZ_W2)
#define SZ_WM  ((size_t)1024*6144)
#define B_WMLO (B_WMHI+SZ_WM)
#define BF_TOTAL (B_WMLO+SZ_WM)

__device__ __nv_bfloat16 g_bf[BF_TOTAL];

// per-direction, per-b-group (4), per-jh-block (16) flags: one per 128B line
#define FLAG_STRIDE 32
__device__ unsigned g_flags[2][4][16][FLAG_STRIDE];
#define NFLAGWORDS (2 * 4 * 16 * FLAG_STRIDE)

// ---------------- small prep kernels (unchanged, R9-proven) ----------------
__global__ void k_embed_split(const int* __restrict__ wid, const int* __restrict__ pid,
                              const float* __restrict__ wl, const float* __restrict__ pl,
                              __nv_bfloat16* __restrict__ hi, __nv_bfloat16* __restrict__ lo)
{
    int i = blockIdx.x * 256 + threadIdx.x;
    if (i >= MROWS * 192) return;
    int col = i % 192, bs = i / 192;
    float v = 0.f;
    if (col < 128)      v = wl[(size_t)wid[bs] * 128 + col];
    else if (col < 160) v = pl[(size_t)pid[bs] * 32 + (col - 128)];
    __nv_bfloat16 h = __float2bfloat16(v);
    hi[i] = h;
    lo[i] = __float2bfloat16(v - __bfloat162float(h));
}

__global__ void k_wsplit(const float* __restrict__ W0, const float* __restrict__ W1,
                         int N0, int Ksrc, int Kpad,
                         __nv_bfloat16* __restrict__ hi, __nv_bfloat16* __restrict__ lo, int total)
{
    int i = blockIdx.x * 256 + threadIdx.x;
    if (i >= total) return;
    int row = i / Kpad, col = i % Kpad;
    float v = 0.f;
    if (col < Ksrc)
        v = (row < N0) ? W0[(size_t)row * Ksrc + col]
                       : W1[(size_t)(row - N0) * Ksrc + col];
    __nv_bfloat16 h = __float2bfloat16(v);
    hi[i] = h;
    lo[i] = __float2bfloat16(v - __bfloat162float(h));
}

__global__ void k_bias2(const float* a, const float* b, const float* c, const float* d,
                        float* __restrict__ o)
{
    int i = blockIdx.x * 256 + threadIdx.x;
    if (i >= 2048) return;
    o[i] = (i < 1024) ? a[i] + b[i] : c[i - 1024] + d[i - 1024];
}

__global__ void k_bcat(const float* a, const float* b, float* __restrict__ o)
{
    int i = blockIdx.x * 256 + threadIdx.x;
    if (i >= 1024) return;
    o[i] = (i < 512) ? a[i] : b[i - 512];
}

__global__ void k_whht_all(const float* __restrict__ w0, const float* __restrict__ w1,
                           const float* __restrict__ w2, const float* __restrict__ w3,
                           float* __restrict__ o, float* __restrict__ hTf, float* __restrict__ hTb)
{
    int i = blockIdx.x * 256 + threadIdx.x;
    if (i < 4 * 262144) {
        int which = i >> 18, local = i & 262143;
        int k = local >> 10, rem = local & 1023, jh = rem >> 2, g = rem & 3;
        const float* w = (which == 0) ? w0 : (which == 1) ? w1 : (which == 2) ? w2 : w3;
        o[i] = w[((g << 8) + jh) * HHID + k];
    }
    if (i < 2 * (int)SZ_HT) {
        if (i < (int)SZ_HT) hTf[i] = 0.f;
        else                hTb[i - SZ_HT] = 0.f;
    }
    if (i < NFLAGWORDS) ((unsigned*)g_flags)[i] = 0u;
}

__global__ void k_owt(const float* __restrict__ outL, const float* __restrict__ routL,
                      float* __restrict__ owT)
{
    int i = blockIdx.x * 256 + threadIdx.x;
    if (i >= 512 * 96) return;
    int h = i / 96, o = i % 96;
    owT[i] = (o < 3) ? outL[o * 512 + h] : routL[(o - 3) * 512 + h];
}

__global__ void k_reset2(float* __restrict__ hTf, float* __restrict__ hTb)
{
    int i = blockIdx.x * 256 + threadIdx.x;
    if (i < 2 * (int)SZ_HT) {
        if (i < (int)SZ_HT) hTf[i] = 0.f;
        else                hTb[i - SZ_HT] = 0.f;
    }
    if (i < NFLAGWORDS) ((unsigned*)g_flags)[i] = 0u;
}

// ---------------- persistent biLSTM recurrence (k-split + b-group barrier) ---
__global__ void __launch_bounds__(256, 1) k_recur(
    const float* __restrict__ xgf, const float* __restrict__ xgb,
    const float* __restrict__ wtf, const float* __restrict__ wtb,
    __nv_bfloat16* __restrict__ vhi, __nv_bfloat16* __restrict__ vlo,
    float* __restrict__ hTf, float* __restrict__ hTb)
{
    extern __shared__ float sm[];
    float* sh_w    = sm;            // [256 k][16 jh][4 gates]
    float* sh_h    = sm + 16384;    // [256 k][16 b]
    float* sh_part = sm + 20480;    // [8 warp][256 cell][4 gates]

    const int tid  = threadIdx.x;
    const int wid  = tid >> 5;
    const int lane = tid & 31;
    const int dir  = blockIdx.x >> 6;
    const int sub  = blockIdx.x & 63;
    const int b0i  = sub & 3;
    const int jh0i = sub >> 2;
    const int b0   = b0i * 16;
    const int jh0  = jh0i * 16;
    const int bl   = tid >> 4, jhl = tid & 15;
    const int b    = b0 + bl,  jh  = jh0 + jhl;
    const int bl2  = lane & 15;
    const int hf   = lane >> 4;

    const float* xg = dir ? xgb : xgf;
    const float* wt = dir ? wtb : wtf;
    float*       hT = dir ? hTb : hTf;

    for (int idx = tid; idx < 16384; idx += 256) {
        int k = idx >> 6, r = idx & 63;
        sh_w[idx] = wt[k * 1024 + jh0 * 4 + r];
    }

    float c = 0.f;
    __syncthreads();

    int s0 = dir ? (SSEQ - 1) : 0;
    const float* xr0 = xg + ((size_t)(b * SSEQ + s0)) * 1024 + jh;
    float ai = __ldg(xr0 +   0);
    float af = __ldg(xr0 + 256);
    float ag = __ldg(xr0 + 512);
    float ao = __ldg(xr0 + 768);

    unsigned* myflag   = &g_flags[dir][b0i][jh0i][0];
    unsigned* pollflag = &g_flags[dir][b0i][tid & 15][0];

    const int k0w = wid * 32;

    for (int it = 0; it < SSEQ; ++it) {
        const float* hcur = hT + (it & 1) * (HHID * BBATCH);
        float*       hnxt = hT + ((it & 1) ^ 1) * (HHID * BBATCH);

        for (int idx = lane; idx < 512; idx += 32) {
            int kk = k0w + (idx >> 4), bb = idx & 15;
            sh_h[kk * 16 + bb] = __ldcg(hcur + kk * 64 + b0 + bb);
        }
        __syncwarp();

        float acc[8][4];
        #pragma unroll
        for (int j = 0; j < 8; ++j)
            #pragma unroll
            for (int g = 0; g < 4; ++g) acc[j][g] = 0.f;

        #pragma unroll 2
        for (int kk = 0; kk < 32; ++kk) {
            int k = k0w + kk;
            float hv = sh_h[k * 16 + bl2];
            const float4* wr = (const float4*)(sh_w + k * 64) + hf * 8;
            #pragma unroll
            for (int j = 0; j < 8; ++j) {
                float4 wv = wr[j];
                acc[j][0] = fmaf(hv, wv.x, acc[j][0]);
                acc[j][1] = fmaf(hv, wv.y, acc[j][1]);
                acc[j][2] = fmaf(hv, wv.z, acc[j][2]);
                acc[j][3] = fmaf(hv, wv.w, acc[j][3]);
            }
        }

        #pragma unroll
        for (int j = 0; j < 8; ++j) {
            int cell = bl2 * 16 + hf * 8 + j;
            *(float4*)(sh_part + wid * 1024 + cell * 4) =
                make_float4(acc[j][0], acc[j][1], acc[j][2], acc[j][3]);
        }
        __syncthreads();

        float si = ai, sf = af, sg = ag, so = ao;
        #pragma unroll
        for (int w = 0; w < 8; ++w) {
            float4 p = *(const float4*)(sh_part + w * 1024 + tid * 4);
            si += p.x; sf += p.y; sg += p.z; so += p.w;
        }

        const int s = dir ? (SSEQ - 1 - it) : it;
        float ig = 1.f / (1.f + expf(-si));
        float fg = 1.f / (1.f + expf(-sf));
        float gv = tanhf(sg);
        float og = 1.f / (1.f + expf(-so));
        c = fmaf(fg, c, ig * gv);
        float h = og * tanhf(c);

        __stcg(hnxt + jh * 64 + b, h);

        // arrival (release)
        __threadfence();
        __syncthreads();
        unsigned epoch = (unsigned)(it + 1);
        if (tid == 0) {
            asm volatile("st.relaxed.gpu.global.u32 [%0], %1;"
                         :: "l"(myflag), "r"(epoch) : "memory");
        }

        // overlapped epilogue
        size_t off = ((size_t)(b * SSEQ + s)) * 512 + (dir << 8) + jh;
        __nv_bfloat16 hh = __float2bfloat16(h);
        vhi[off] = hh;
        vlo[off] = __float2bfloat16(h - __bfloat162float(hh));
        if (it + 1 < SSEQ) {
            const int sn = dir ? (SSEQ - 2 - it) : (it + 1);
            const float* xrn = xg + ((size_t)(b * SSEQ + sn)) * 1024 + jh;
            ai = __ldg(xrn +   0);
            af = __ldg(xrn + 256);
            ag = __ldg(xrn + 512);
            ao = __ldg(xrn + 768);
        }

        // wait (acquire): 16 same-b0 blocks
        if (tid < 16) {
            unsigned v;
            do {
                asm volatile("ld.relaxed.gpu.global.u32 %0, [%1];"
                             : "=r"(v) : "l"(pollflag) : "memory");
            } while (v < epoch);
            __threadfence();
        }
        __syncthreads();
    }
}

// ---------------- HMMA bf16 3-product split GEMM, double-buffered, 2 CTA/SM --
#define KC    32
#define TROWB 80
#define TILE2 10240
#define STG   40960
#define NST   2

__device__ __forceinline__ uint32_t smem_u32(const void* p) {
    uint32_t a;
    asm("{ .reg .u64 t; cvta.to.shared.u64 t, %1; cvt.u32.u64 %0, t; }"
        : "=r"(a) : "l"(p));
    return a;
}
__device__ __forceinline__ void cpasync16(uint32_t dst, const void* src) {
    asm volatile("cp.async.ca.shared.global [%0], [%1], 16;" :: "r"(dst), "l"(src));
}
#define CP_COMMIT() asm volatile("cp.async.commit_group;" ::: "memory")
#define CP_WAIT1()  asm volatile("cp.async.wait_group 1;" ::: "memory")
#define CP_WAIT0()  asm volatile("cp.async.wait_group 0;" ::: "memory")

__device__ __forceinline__ void ldsm4(uint32_t addr, uint32_t* r) {
    asm volatile("ldmatrix.sync.aligned.m8n8.x4.shared.b16 {%0,%1,%2,%3}, [%4];"
        : "=r"(r[0]), "=r"(r[1]), "=r"(r[2]), "=r"(r[3]) : "r"(addr));
}

__device__ __forceinline__ void mma16816(float* d, const uint32_t* a, const uint32_t* b) {
    asm volatile(
        "mma.sync.aligned.m16n8k16.row.col.f32.bf16.bf16.f32 "
        "{%0,%1,%2,%3}, {%4,%5,%6,%7}, {%8,%9}, {%0,%1,%2,%3};"
        : "+f"(d[0]), "+f"(d[1]), "+f"(d[2]), "+f"(d[3])
        : "r"(a[0]), "r"(a[1]), "r"(a[2]), "r"(a[3]), "r"(b[0]), "r"(b[1]));
}

template<bool GATHER>
__device__ __forceinline__ void issue_stage(
    uint32_t sbase, int stage, int c, int row0, int n0, int KU,
    const uint4* A4h, const uint4* A4l, const uint4* W4h, const uint4* W4l,
    const int* fidx, int tid)
{
    const int k0 = c * KC;
    const uint32_t dstb = sbase + stage * STG;
    #pragma unroll
    for (int u0 = 0; u0 < 2048; u0 += 256) {
        int u = u0 + tid;
        int tile = u >> 9;
        int v = u & 511;
        int r = v >> 2, j = v & 3;
        const uint4* src;
        if (tile < 2) {
            const uint4* base = tile ? A4l : A4h;
            if (GATHER) {
                int m    = row0 + r;
                int slot = k0 >> 9;
                int fi   = __ldg(fidx + m * 12 + slot);
                int srow = ((m >> 8) << 8) + fi;
                src = base + (size_t)srow * 64 + ((k0 & 511) >> 3) + j;
            } else {
                src = base + (size_t)(row0 + r) * KU + (k0 >> 3) + j;
            }
        } else {
            const uint4* base = (tile == 3) ? W4l : W4h;
            src = base + (size_t)(n0 + r) * KU + (k0 >> 3) + j;
        }
        cpasync16(dstb + tile * TILE2 + r * TROWB + j * 16, src);
    }
    CP_COMMIT();
}

template<bool GATHER, bool TANH>
__global__ void __launch_bounds__(256, 2) k_hmma(
    const __nv_bfloat16* __restrict__ Ahi, const __nv_bfloat16* __restrict__ Alo,
    const __nv_bfloat16* __restrict__ Whi, const __nv_bfloat16* __restrict__ Wlo,
    const float* __restrict__ bias, float* __restrict__ C0, float* __restrict__ C1,
    int halfN, int Kpad, const int* __restrict__ fidx)
{
    extern __shared__ __align__(16) char smem[];
    const uint32_t sb = smem_u32(smem);
    const int tid  = threadIdx.x;
    const int wid  = tid >> 5;
    const int lane = tid & 31;
    const int grp  = lane >> 2;
    const int quad = lane & 3;
    const int row0 = blockIdx.y * 128;
    const int n0   = blockIdx.x * 128;
    const int wm   = (wid & 3) * 32;
    const int wn   = (wid >> 2) * 64;

    const int lg = lane >> 3;
    const uint32_t aoff = ((lane & 7) + ((lg & 1) << 3)) * TROWB + ((lg >> 1) << 4);
    const uint32_t boff = ((lane & 7) + ((lg >> 1) << 3)) * TROWB + ((lg & 1) << 4);

    const int KU = Kpad >> 3;
    const uint4* A4h = (const uint4*)Ahi;
    const uint4* A4l = (const uint4*)Alo;
    const uint4* W4h = (const uint4*)Whi;
    const uint4* W4l = (const uint4*)Wlo;

    float acc[2][8][4];
    #pragma unroll
    for (int i = 0; i < 2; ++i)
        #pragma unroll
        for (int j = 0; j < 8; ++j)
            #pragma unroll
            for (int q = 0; q < 4; ++q) acc[i][j][q] = 0.f;

    const int nch = Kpad / KC;
    issue_stage<GATHER>(sb, 0, 0, row0, n0, KU, A4h, A4l, W4h, W4l, fidx, tid);

    for (int c = 0; c < nch; ++c) {
        __syncthreads();
        if (c + 1 < nch) {
            issue_stage<GATHER>(sb, (c + 1) & 1, c + 1, row0, n0, KU,
                                A4h, A4l, W4h, W4l, fidx, tid);
            CP_WAIT1();
        } else {
            CP_WAIT0();
        }
        __syncthreads();

        const uint32_t bufa = sb + (c & 1) * STG;
        #pragma unroll
        for (int ks = 0; ks < 2; ++ks) {
            uint32_t ah[8], al[8];
            #pragma unroll
            for (int mt = 0; mt < 2; ++mt) {
                uint32_t addr = bufa + (uint32_t)(wm + mt * 16) * TROWB + ks * 32 + aoff;
                ldsm4(addr,          ah + mt * 4);
                ldsm4(addr + TILE2,  al + mt * 4);
            }
            #pragma unroll
            for (int np = 0; np < 4; ++np) {
                uint32_t bh[4], bl[4];
                uint32_t addr = bufa + 2 * TILE2 + (uint32_t)(wn + np * 16) * TROWB + ks * 32 + boff;
                ldsm4(addr,          bh);
                ldsm4(addr + TILE2,  bl);
                // product passes over all 4 (mt,nh) targets: 3 independent
                // HMMAs between successive writes to the same accumulator.
                // Per-acc accumulation order unchanged: hi*hi, hi*lo, lo*hi.
                #pragma unroll
                for (int mt = 0; mt < 2; ++mt)
                    #pragma unroll
                    for (int nh = 0; nh < 2; ++nh)
                        mma16816(acc[mt][np * 2 + nh], ah + mt * 4, bh + nh * 2);
                #pragma unroll
                for (int mt = 0; mt < 2; ++mt)
                    #pragma unroll
                    for (int nh = 0; nh < 2; ++nh)
                        mma16816(acc[mt][np * 2 + nh], ah + mt * 4, bl + nh * 2);
                #pragma unroll
                for (int mt = 0; mt < 2; ++mt)
                    #pragma unroll
                    for (int nh = 0; nh < 2; ++nh)
                        mma16816(acc[mt][np * 2 + nh], al + mt * 4, bh + nh * 2);
            }
        }
    }

    const int gbase = n0 + wn;
    float* Co;
    int cbase;
    if (gbase < halfN) { Co = C0; cbase = gbase; }
    else               { Co = C1; cbase = gbase - halfN; }

    #pragma unroll
    for (int mt = 0; mt < 2; ++mt) {
        int r = row0 + wm + mt * 16 + grp;
        #pragma unroll
        for (int nt = 0; nt < 8; ++nt) {
            int gc = gbase + nt * 8 + quad * 2;
            float b0v = bias[gc], b1v = bias[gc + 1];
            float v0 = acc[mt][nt][0] + b0v;
            float v1 = acc[mt][nt][1] + b1v;
            float v2 = acc[mt][nt][2] + b0v;
            float v3 = acc[mt][nt][3] + b1v;
            if (TANH) { v0 = tanhf(v0); v1 = tanhf(v1); v2 = tanhf(v2); v3 = tanhf(v3); }
            int cc = cbase + nt * 8 + quad * 2;
            *(float2*)(Co + (size_t)r * halfN + cc)       = make_float2(v0, v1);
            *(float2*)(Co + (size_t)(r + 8) * halfN + cc) = make_float2(v2, v3);
        }
    }
}

// ---------------- tiled output head: 16 bt rows per block --------------------
__global__ void __launch_bounds__(256) k_out2(
    const float* __restrict__ hid, const float* __restrict__ rhid,
    const float* __restrict__ owT, const float* __restrict__ ob,
    const float* __restrict__ rb, float* __restrict__ out)
{
    extern __shared__ float sh[];
    const int tid = threadIdx.x;
    const int bt0 = blockIdx.x * 16;

    for (int i = tid; i < 16 * 512; i += 256) {
        int r = i >> 9, cc = i & 511;
        sh[r * 1024 + cc]       = hid[(size_t)(bt0 + r) * 512 + cc];
        sh[r * 1024 + 512 + cc] = rhid[(size_t)(bt0 + r) * 512 + cc];
    }
    __syncthreads();

    #pragma unroll
    for (int p0 = 0; p0 < 16 * 96; p0 += 256) {
        int p = p0 + tid;
        int row = p / 96, o = p % 96;
        const float* base = sh + row * 1024 + ((o < 3) ? 0 : 512);
        float acc = 0.f;
        #pragma unroll 8
        for (int h = 0; h < 512; ++h)
            acc = fmaf(__ldg(owT + h * 96 + o), base[h], acc);
        int bt = bt0 + row;
        if (o < 3) out[(size_t)bt * 3 + o] = acc + ob[o];
        else       out[(size_t)BTROWS * 3 + (size_t)bt * 93 + (o - 3)] = acc + rb[o - 3];
    }
}

// ---------------- launch ------------------------------------------------------
extern "C" void kernel_launch(void* const* d_in, const int* in_sizes, int n_in,
                              void* d_out, int out_size)
{
    const int*   wid   = (const int*)d_in[0];
    const int*   pid   = (const int*)d_in[1];
    const int*   fidx  = (const int*)d_in[2];
    const float* wl    = (const float*)d_in[3];
    const float* pl    = (const float*)d_in[4];
    const float* Wih1f = (const float*)d_in[5];
    const float* Whh1f = (const float*)d_in[6];
    const float* bih1f = (const float*)d_in[7];
    const float* bhh1f = (const float*)d_in[8];
    const float* Wih1b = (const float*)d_in[9];
    const float* Whh1b = (const float*)d_in[10];
    const float* bih1b = (const float*)d_in[11];
    const float* bhh1b = (const float*)d_in[12];
    const float* Wih2f = (const float*)d_in[13];
    const float* Whh2f = (const float*)d_in[14];
    const float* bih2f = (const float*)d_in[15];
    const float* bhh2f = (const float*)d_in[16];
    const float* Wih2b = (const float*)d_in[17];
    const float* Whh2b = (const float*)d_in[18];
    const float* bih2b = (const float*)d_in[19];
    const float* bhh2b = (const float*)d_in[20];
    const float* hidL  = (const float*)d_in[21];
    const float* hidB  = (const float*)d_in[22];
    const float* outL  = (const float*)d_in[23];
    const float* outB  = (const float*)d_in[24];
    const float* rhidL = (const float*)d_in[25];
    const float* rhidB = (const float*)d_in[26];
    const float* routL = (const float*)d_in[27];
    const float* routB = (const float*)d_in[28];
    float* out = (float*)d_out;

    float* scr = nullptr;
    cudaGetSymbolAddress((void**)&scr, g_f32);
    __nv_bfloat16* bfp = nullptr;
    cudaGetSymbolAddress((void**)&bfp, g_bf);

    float* xgf  = scr + O_XGF;
    float* xgb  = scr + O_XGB;
    float* hid  = scr + O_HID;
    float* rhid = scr + O_RHID;
    float* whht = scr + O_WHHT;
    float* hTf  = scr + O_HTF;
    float* hTb  = scr + O_HTB;
    float* owT  = scr + O_OWT;
    float* bs1  = scr + O_BS1;
    float* bs2  = scr + O_BS2;
    float* bsm  = scr + O_BSM;

    __nv_bfloat16* ivhi = bfp + B_IVHI;
    __nv_bfloat16* ivlo = bfp + B_IVLO;
    __nv_bfloat16* avhi = bfp + B_AVHI;
    __nv_bfloat16* avlo = bfp + B_AVLO;
    __nv_bfloat16* v2hi = bfp + B_V2HI;
    __nv_bfloat16* v2lo = bfp + B_V2LO;
    __nv_bfloat16* w1hi = bfp + B_W1HI;
    __nv_bfloat16* w1lo = bfp + B_W1LO;
    __nv_bfloat16* w2hi = bfp + B_W2HI;
    __nv_bfloat16* w2lo = bfp + B_W2LO;
    __nv_bfloat16* wmhi = bfp + B_WMHI;
    __nv_bfloat16* wmlo = bfp + B_WMLO;

    cudaFuncSetAttribute(k_recur, cudaFuncAttributeMaxDynamicSharedMemorySize, 114688);
    cudaFuncSetAttribute(k_hmma<false, false>, cudaFuncAttributeMaxDynamicSharedMemorySize, NST * STG);
    cudaFuncSetAttribute(k_hmma<true, true>,  cudaFuncAttributeMaxDynamicSharedMemorySize, NST * STG);
    cudaFuncSetAttribute(k_out2, cudaFuncAttributeMaxDynamicSharedMemorySize, 65536);

    dim3 gx(16, 128);
    // 0: embeddings
    k_embed_split<<<(MROWS * 192 + 255) / 256, 256>>>(wid, pid, wl, pl, ivhi, ivlo);
    // 1: layer-1 input weights split
    k_wsplit<<<(2048 * 192 + 255) / 256, 256>>>(Wih1f, Wih1b, 1024, 160, 192, w1hi, w1lo, 2048 * 192);
    // 2: layer-1 bias
    k_bias2<<<8, 256>>>(bih1f, bhh1f, bih1b, bhh1b, bs1);
    // 3: xg GEMM layer 1   <-- ncu capture lands here
    k_hmma<false, false><<<gx, 256, NST * STG>>>(ivhi, ivlo, w1hi, w1lo, bs1, xgf, xgb, 1024, 192, nullptr);
    // 4: Whh transposes + zero hT + zero flags
    k_whht_all<<<4096, 256>>>(Whh1f, Whh1b, Whh2f, Whh2b, whht, hTf, hTb);
    // 5: recurrence layer 1
    k_recur<<<128, 256, 114688>>>(xgf, xgb, whht + 0 * SZ_WHHT, whht + 1 * SZ_WHHT, avhi, avlo, hTf, hTb);
    // 6-8: layer 2
    k_wsplit<<<(2048 * 512 + 255) / 256, 256>>>(Wih2f, Wih2b, 1024, 512, 512, w2hi, w2lo, 2048 * 512);
    k_bias2<<<8, 256>>>(bih2f, bhh2f, bih2b, bhh2b, bs2);
    k_hmma<false, false><<<gx, 256, NST * STG>>>(avhi, avlo, w2hi, w2lo, bs2, xgf, xgb, 1024, 512, nullptr);
    // 9-10: reset + recurrence layer 2
    k_reset2<<<256, 256>>>(hTf, hTb);
    k_recur<<<128, 256, 114688>>>(xgf, xgb, whht + 2 * SZ_WHHT, whht + 3 * SZ_WHHT, v2hi, v2lo, hTf, hTb);
    // 11-13: MLP head prep
    k_wsplit<<<(1024 * 6144 + 255) / 256, 256>>>(hidL, rhidL, 512, 6144, 6144, wmhi, wmlo, 1024 * 6144);
    k_bcat<<<4, 256>>>(hidB, rhidB, bsm);
    k_owt<<<(512 * 96 + 255) / 256, 256>>>(outL, routL, owT);
    // 14: MLP head GEMM (gathered, hid|rhid fused, tanh epilogue)
    dim3 gm(8, 128);
    k_hmma<true, true><<<gm, 256, NST * STG>>>(v2hi, v2lo, wmhi, wmlo, bsm, hid, rhid, 512, 6144, fidx);
    // 15: tiled output head
    k_out2<<<BTROWS / 16, 256, 65536>>>(hid, rhid, owT, outB, routB, out);
}

// round 16
// speedup vs baseline: 1.0423x; 1.0423x over previous
#include <cuda_runtime.h>
#include <cuda_bf16.h>
#include <math.h>
#include <stdint.h>

// ---------------- problem constants ----------------
#define BBATCH 64
#define SSEQ   256
#define HHID   256
#define MROWS  16384
#define BTROWS 16384

// ---------------- fp32 scratch ----------------
#define O_XGF   ((size_t)0)
#define SZ_XG   ((size_t)MROWS*1024)
#define O_XGB   (O_XGF+SZ_XG)
#define O_HID   (O_XGB+SZ_XG)
#define SZ_HID  ((size_t)BTROWS*512)
#define O_RHID  (O_HID+SZ_HID)
#define O_WHHT  (O_RHID+SZ_HID)
#define SZ_WHHT ((size_t)HHID*HHID*4)
#define O_HTF   (O_WHHT+4*SZ_WHHT)
#define SZ_HT   ((size_t)2*HHID*BBATCH)
#define O_HTB   (O_HTF+SZ_HT)
#define O_OWT   (O_HTB+SZ_HT)
#define SZ_OWT  ((size_t)512*96)
#define O_BS1   (O_OWT+SZ_OWT)
#define O_BS2   (O_BS1+2048)
#define O_BSM   (O_BS2+2048)
#define F32_TOTAL (O_BSM+1024)

__device__ float g_f32[F32_TOTAL];

// ---------------- bf16 scratch ----------------
#define B_IVHI ((size_t)0)
#define SZ_IV  ((size_t)MROWS*192)
#define B_IVLO (B_IVHI+SZ_IV)
#define B_AVHI (B_IVLO+SZ_IV)
#define SZ_AV  ((size_t)MROWS*512)
#define B_AVLO (B_AVHI+SZ_AV)
#define B_V2HI (B_AVLO+SZ_AV)
#define B_V2LO (B_V2HI+SZ_AV)
#define B_W1HI (B_V2LO+SZ_AV)
#define SZ_W1  ((size_t)2048*192)
#define B_W1LO (B_W1HI+SZ_W1)
#define B_W2HI (B_W1LO+SZ_W1)
#define SZ_W2  ((size_t)2048*512)
#define B_W2LO (B_W2HI+SZ_W2)
#define B_WMHI (B_W2LO+SZ_W2)
#define SZ_WM  ((size_t)1024*6144)
#define B_WMLO (B_WMHI+SZ_WM)
#define BF_TOTAL (B_WMLO+SZ_WM)

__device__ __nv_bfloat16 g_bf[BF_TOTAL];

// per-direction, per-b-group (4), per-jh-block (16) flags: one per 128B line
#define FLAG_STRIDE 32
__device__ unsigned g_flags[2][4][16][FLAG_STRIDE];
#define NFLAGWORDS (2 * 4 * 16 * FLAG_STRIDE)

// ---------------- small prep kernels (unchanged, R9-proven) ----------------
__global__ void k_embed_split(const int* __restrict__ wid, const int* __restrict__ pid,
                              const float* __restrict__ wl, const float* __restrict__ pl,
                              __nv_bfloat16* __restrict__ hi, __nv_bfloat16* __restrict__ lo)
{
    int i = blockIdx.x * 256 + threadIdx.x;
    if (i >= MROWS * 192) return;
    int col = i % 192, bs = i / 192;
    float v = 0.f;
    if (col < 128)      v = wl[(size_t)wid[bs] * 128 + col];
    else if (col < 160) v = pl[(size_t)pid[bs] * 32 + (col - 128)];
    __nv_bfloat16 h = __float2bfloat16(v);
    hi[i] = h;
    lo[i] = __float2bfloat16(v - __bfloat162float(h));
}

__global__ void k_wsplit(const float* __restrict__ W0, const float* __restrict__ W1,
                         int N0, int Ksrc, int Kpad,
                         __nv_bfloat16* __restrict__ hi, __nv_bfloat16* __restrict__ lo, int total)
{
    int i = blockIdx.x * 256 + threadIdx.x;
    if (i >= total) return;
    int row = i / Kpad, col = i % Kpad;
    float v = 0.f;
    if (col < Ksrc)
        v = (row < N0) ? W0[(size_t)row * Ksrc + col]
                       : W1[(size_t)(row - N0) * Ksrc + col];
    __nv_bfloat16 h = __float2bfloat16(v);
    hi[i] = h;
    lo[i] = __float2bfloat16(v - __bfloat162float(h));
}

__global__ void k_bias2(const float* a, const float* b, const float* c, const float* d,
                        float* __restrict__ o)
{
    int i = blockIdx.x * 256 + threadIdx.x;
    if (i >= 2048) return;
    o[i] = (i < 1024) ? a[i] + b[i] : c[i - 1024] + d[i - 1024];
}

__global__ void k_bcat(const float* a, const float* b, float* __restrict__ o)
{
    int i = blockIdx.x * 256 + threadIdx.x;
    if (i >= 1024) return;
    o[i] = (i < 512) ? a[i] : b[i - 512];
}

__global__ void k_whht_all(const float* __restrict__ w0, const float* __restrict__ w1,
                           const float* __restrict__ w2, const float* __restrict__ w3,
                           float* __restrict__ o, float* __restrict__ hTf, float* __restrict__ hTb)
{
    int i = blockIdx.x * 256 + threadIdx.x;
    if (i < 4 * 262144) {
        int which = i >> 18, local = i & 262143;
        int k = local >> 10, rem = local & 1023, jh = rem >> 2, g = rem & 3;
        const float* w = (which == 0) ? w0 : (which == 1) ? w1 : (which == 2) ? w2 : w3;
        o[i] = w[((g << 8) + jh) * HHID + k];
    }
    if (i < 2 * (int)SZ_HT) {
        if (i < (int)SZ_HT) hTf[i] = 0.f;
        else                hTb[i - SZ_HT] = 0.f;
    }
    if (i < NFLAGWORDS) ((unsigned*)g_flags)[i] = 0u;
}

__global__ void k_owt(const float* __restrict__ outL, const float* __restrict__ routL,
                      float* __restrict__ owT)
{
    int i = blockIdx.x * 256 + threadIdx.x;
    if (i >= 512 * 96) return;
    int h = i / 96, o = i % 96;
    owT[i] = (o < 3) ? outL[o * 512 + h] : routL[(o - 3) * 512 + h];
}

__global__ void k_reset2(float* __restrict__ hTf, float* __restrict__ hTb)
{
    int i = blockIdx.x * 256 + threadIdx.x;
    if (i < 2 * (int)SZ_HT) {
        if (i < (int)SZ_HT) hTf[i] = 0.f;
        else                hTb[i - SZ_HT] = 0.f;
    }
    if (i < NFLAGWORDS) ((unsigned*)g_flags)[i] = 0u;
}

// ---------------- fast activations (error ~1e-6, margin 50x) ----------------
__device__ __forceinline__ float fsigmoid(float x) {
    return __fdividef(1.f, 1.f + __expf(-x));
}
__device__ __forceinline__ float ftanh(float x) {
    float t = __expf(-2.f * x);
    return __fdividef(1.f - t, 1.f + t);
}

// ---------------- persistent biLSTM recurrence -------------------------------
// k-split across warps; h staged directly into REGISTERS (no sh_h);
// fast activations; b-group barrier (R14-proven).
__global__ void __launch_bounds__(256, 1) k_recur(
    const float* __restrict__ xgf, const float* __restrict__ xgb,
    const float* __restrict__ wtf, const float* __restrict__ wtb,
    __nv_bfloat16* __restrict__ vhi, __nv_bfloat16* __restrict__ vlo,
    float* __restrict__ hTf, float* __restrict__ hTb)
{
    extern __shared__ float sm[];
    float* sh_w    = sm;            // [256 k][16 jh][4 gates]  (64 KB)
    float* sh_part = sm + 16384;    // [8 warp][256 cell][4 gates] (32 KB)

    const int tid  = threadIdx.x;
    const int wid  = tid >> 5;
    const int lane = tid & 31;
    const int dir  = blockIdx.x >> 6;
    const int sub  = blockIdx.x & 63;
    const int b0i  = sub & 3;
    const int jh0i = sub >> 2;
    const int b0   = b0i * 16;
    const int jh0  = jh0i * 16;
    const int bl   = tid >> 4, jhl = tid & 15;
    const int b    = b0 + bl,  jh  = jh0 + jhl;
    const int bl2  = lane & 15;
    const int hf   = lane >> 4;

    const float* xg = dir ? xgb : xgf;
    const float* wt = dir ? wtb : wtf;
    float*       hT = dir ? hTb : hTf;

    for (int idx = tid; idx < 16384; idx += 256) {
        int k = idx >> 6, r = idx & 63;
        sh_w[idx] = wt[k * 1024 + jh0 * 4 + r];
    }

    float c = 0.f;
    __syncthreads();

    int s0 = dir ? (SSEQ - 1) : 0;
    const float* xr0 = xg + ((size_t)(b * SSEQ + s0)) * 1024 + jh;
    float ai = __ldg(xr0 +   0);
    float af = __ldg(xr0 + 256);
    float ag = __ldg(xr0 + 512);
    float ao = __ldg(xr0 + 768);

    unsigned* myflag   = &g_flags[dir][b0i][jh0i][0];
    unsigned* pollflag = &g_flags[dir][b0i][tid & 15][0];

    const int k0w = wid * 32;

    for (int it = 0; it < SSEQ; ++it) {
        const float* hcur = hT + (it & 1) * (HHID * BBATCH);
        float*       hnxt = hT + ((it & 1) ^ 1) * (HHID * BBATCH);

        // h for this thread's k-range straight into registers (bypass L1)
        float hreg[32];
        #pragma unroll
        for (int kk = 0; kk < 32; ++kk)
            hreg[kk] = __ldcg(hcur + (k0w + kk) * 64 + b0 + bl2);

        float acc[8][4];
        #pragma unroll
        for (int j = 0; j < 8; ++j)
            #pragma unroll
            for (int g = 0; g < 4; ++g) acc[j][g] = 0.f;

        #pragma unroll 2
        for (int kk = 0; kk < 32; ++kk) {
            int k = k0w + kk;
            float hv = hreg[kk];
            const float4* wr = (const float4*)(sh_w + k * 64) + hf * 8;
            #pragma unroll
            for (int j = 0; j < 8; ++j) {
                float4 wv = wr[j];
                acc[j][0] = fmaf(hv, wv.x, acc[j][0]);
                acc[j][1] = fmaf(hv, wv.y, acc[j][1]);
                acc[j][2] = fmaf(hv, wv.z, acc[j][2]);
                acc[j][3] = fmaf(hv, wv.w, acc[j][3]);
            }
        }

        #pragma unroll
        for (int j = 0; j < 8; ++j) {
            int cell = bl2 * 16 + hf * 8 + j;
            *(float4*)(sh_part + wid * 1024 + cell * 4) =
                make_float4(acc[j][0], acc[j][1], acc[j][2], acc[j][3]);
        }
        __syncthreads();

        float si = ai, sf = af, sg = ag, so = ao;
        #pragma unroll
        for (int w = 0; w < 8; ++w) {
            float4 p = *(const float4*)(sh_part + w * 1024 + tid * 4);
            si += p.x; sf += p.y; sg += p.z; so += p.w;
        }

        const int s = dir ? (SSEQ - 1 - it) : it;
        float ig = fsigmoid(si);
        float fg = fsigmoid(sf);
        float gv = ftanh(sg);
        float og = fsigmoid(so);
        c = fmaf(fg, c, ig * gv);
        float h = og * ftanh(c);

        __stcg(hnxt + jh * 64 + b, h);

        // arrival (release)
        __threadfence();
        __syncthreads();
        unsigned epoch = (unsigned)(it + 1);
        if (tid == 0) {
            asm volatile("st.relaxed.gpu.global.u32 [%0], %1;"
                         :: "l"(myflag), "r"(epoch) : "memory");
        }

        // overlapped epilogue
        size_t off = ((size_t)(b * SSEQ + s)) * 512 + (dir << 8) + jh;
        __nv_bfloat16 hh = __float2bfloat16(h);
        vhi[off] = hh;
        vlo[off] = __float2bfloat16(h - __bfloat162float(hh));
        if (it + 1 < SSEQ) {
            const int sn = dir ? (SSEQ - 2 - it) : (it + 1);
            const float* xrn = xg + ((size_t)(b * SSEQ + sn)) * 1024 + jh;
            ai = __ldg(xrn +   0);
            af = __ldg(xrn + 256);
            ag = __ldg(xrn + 512);
            ao = __ldg(xrn + 768);
        }

        // wait (acquire): 16 same-b0 blocks
        if (tid < 16) {
            unsigned v;
            do {
                asm volatile("ld.relaxed.gpu.global.u32 %0, [%1];"
                             : "=r"(v) : "l"(pollflag) : "memory");
            } while (v < epoch);
            __threadfence();
        }
        __syncthreads();
    }
}

// ---------------- HMMA bf16 3-product split GEMM, double-buffered, 2 CTA/SM --
#define KC    32
#define TROWB 80
#define TILE2 10240
#define STG   40960
#define NST   2

__device__ __forceinline__ uint32_t smem_u32(const void* p) {
    uint32_t a;
    asm("{ .reg .u64 t; cvta.to.shared.u64 t, %1; cvt.u32.u64 %0, t; }"
        : "=r"(a) : "l"(p));
    return a;
}
__device__ __forceinline__ void cpasync16(uint32_t dst, const void* src) {
    asm volatile("cp.async.ca.shared.global [%0], [%1], 16;" :: "r"(dst), "l"(src));
}
#define CP_COMMIT() asm volatile("cp.async.commit_group;" ::: "memory")
#define CP_WAIT1()  asm volatile("cp.async.wait_group 1;" ::: "memory")
#define CP_WAIT0()  asm volatile("cp.async.wait_group 0;" ::: "memory")

__device__ __forceinline__ void ldsm4(uint32_t addr, uint32_t* r) {
    asm volatile("ldmatrix.sync.aligned.m8n8.x4.shared.b16 {%0,%1,%2,%3}, [%4];"
        : "=r"(r[0]), "=r"(r[1]), "=r"(r[2]), "=r"(r[3]) : "r"(addr));
}

__device__ __forceinline__ void mma16816(float* d, const uint32_t* a, const uint32_t* b) {
    asm volatile(
        "mma.sync.aligned.m16n8k16.row.col.f32.bf16.bf16.f32 "
        "{%0,%1,%2,%3}, {%4,%5,%6,%7}, {%8,%9}, {%0,%1,%2,%3};"
        : "+f"(d[0]), "+f"(d[1]), "+f"(d[2]), "+f"(d[3])
        : "r"(a[0]), "r"(a[1]), "r"(a[2]), "r"(a[3]), "r"(b[0]), "r"(b[1]));
}

template<bool GATHER>
__device__ __forceinline__ void issue_stage(
    uint32_t sbase, int stage, int c, int row0, int n0, int KU,
    const uint4* A4h, const uint4* A4l, const uint4* W4h, const uint4* W4l,
    const int* fidx, int tid)
{
    const int k0 = c * KC;
    const uint32_t dstb = sbase + stage * STG;
    #pragma unroll
    for (int u0 = 0; u0 < 2048; u0 += 256) {
        int u = u0 + tid;
        int tile = u >> 9;
        int v = u & 511;
        int r = v >> 2, j = v & 3;
        const uint4* src;
        if (tile < 2) {
            const uint4* base = tile ? A4l : A4h;
            if (GATHER) {
                int m    = row0 + r;
                int slot = k0 >> 9;
                int fi   = __ldg(fidx + m * 12 + slot);
                int srow = ((m >> 8) << 8) + fi;
                src = base + (size_t)srow * 64 + ((k0 & 511) >> 3) + j;
            } else {
                src = base + (size_t)(row0 + r) * KU + (k0 >> 3) + j;
            }
        } else {
            const uint4* base = (tile == 3) ? W4l : W4h;
            src = base + (size_t)(n0 + r) * KU + (k0 >> 3) + j;
        }
        cpasync16(dstb + tile * TILE2 + r * TROWB + j * 16, src);
    }
    CP_COMMIT();
}

template<bool GATHER, bool TANH>
__global__ void __launch_bounds__(256, 2) k_hmma(
    const __nv_bfloat16* __restrict__ Ahi, const __nv_bfloat16* __restrict__ Alo,
    const __nv_bfloat16* __restrict__ Whi, const __nv_bfloat16* __restrict__ Wlo,
    const float* __restrict__ bias, float* __restrict__ C0, float* __restrict__ C1,
    int halfN, int Kpad, const int* __restrict__ fidx)
{
    extern __shared__ __align__(16) char smem[];
    const uint32_t sb = smem_u32(smem);
    const int tid  = threadIdx.x;
    const int wid  = tid >> 5;
    const int lane = tid & 31;
    const int grp  = lane >> 2;
    const int quad = lane & 3;
    const int row0 = blockIdx.y * 128;
    const int n0   = blockIdx.x * 128;
    const int wm   = (wid & 3) * 32;
    const int wn   = (wid >> 2) * 64;

    const int lg = lane >> 3;
    const uint32_t aoff = ((lane & 7) + ((lg & 1) << 3)) * TROWB + ((lg >> 1) << 4);
    const uint32_t boff = ((lane & 7) + ((lg >> 1) << 3)) * TROWB + ((lg & 1) << 4);

    const int KU = Kpad >> 3;
    const uint4* A4h = (const uint4*)Ahi;
    const uint4* A4l = (const uint4*)Alo;
    const uint4* W4h = (const uint4*)Whi;
    const uint4* W4l = (const uint4*)Wlo;

    float acc[2][8][4];
    #pragma unroll
    for (int i = 0; i < 2; ++i)
        #pragma unroll
        for (int j = 0; j < 8; ++j)
            #pragma unroll
            for (int q = 0; q < 4; ++q) acc[i][j][q] = 0.f;

    const int nch = Kpad / KC;
    issue_stage<GATHER>(sb, 0, 0, row0, n0, KU, A4h, A4l, W4h, W4l, fidx, tid);

    for (int c = 0; c < nch; ++c) {
        __syncthreads();
        if (c + 1 < nch) {
            issue_stage<GATHER>(sb, (c + 1) & 1, c + 1, row0, n0, KU,
                                A4h, A4l, W4h, W4l, fidx, tid);
            CP_WAIT1();
        } else {
            CP_WAIT0();
        }
        __syncthreads();

        const uint32_t bufa = sb + (c & 1) * STG;
        #pragma unroll
        for (int ks = 0; ks < 2; ++ks) {
            uint32_t ah[8], al[8];
            #pragma unroll
            for (int mt = 0; mt < 2; ++mt) {
                uint32_t addr = bufa + (uint32_t)(wm + mt * 16) * TROWB + ks * 32 + aoff;
                ldsm4(addr,          ah + mt * 4);
                ldsm4(addr + TILE2,  al + mt * 4);
            }
            #pragma unroll
            for (int np = 0; np < 4; ++np) {
                uint32_t bh[4], bl[4];
                uint32_t addr = bufa + 2 * TILE2 + (uint32_t)(wn + np * 16) * TROWB + ks * 32 + boff;
                ldsm4(addr,          bh);
                ldsm4(addr + TILE2,  bl);
                #pragma unroll
                for (int mt = 0; mt < 2; ++mt)
                    #pragma unroll
                    for (int nh = 0; nh < 2; ++nh) {
                        int nt = np * 2 + nh;
                        mma16816(acc[mt][nt], ah + mt * 4, bh + nh * 2);
                        mma16816(acc[mt][nt], ah + mt * 4, bl + nh * 2);
                        mma16816(acc[mt][nt], al + mt * 4, bh + nh * 2);
                    }
            }
        }
    }

    const int gbase = n0 + wn;
    float* Co;
    int cbase;
    if (gbase < halfN) { Co = C0; cbase = gbase; }
    else               { Co = C1; cbase = gbase - halfN; }

    #pragma unroll
    for (int mt = 0; mt < 2; ++mt) {
        int r = row0 + wm + mt * 16 + grp;
        #pragma unroll
        for (int nt = 0; nt < 8; ++nt) {
            int gc = gbase + nt * 8 + quad * 2;
            float b0v = bias[gc], b1v = bias[gc + 1];
            float v0 = acc[mt][nt][0] + b0v;
            float v1 = acc[mt][nt][1] + b1v;
            float v2 = acc[mt][nt][2] + b0v;
            float v3 = acc[mt][nt][3] + b1v;
            if (TANH) { v0 = tanhf(v0); v1 = tanhf(v1); v2 = tanhf(v2); v3 = tanhf(v3); }
            int cc = cbase + nt * 8 + quad * 2;
            *(float2*)(Co + (size_t)r * halfN + cc)       = make_float2(v0, v1);
            *(float2*)(Co + (size_t)(r + 8) * halfN + cc) = make_float2(v2, v3);
        }
    }
}

// ---------------- tiled output head: 16 bt rows per block --------------------
__global__ void __launch_bounds__(256) k_out2(
    const float* __restrict__ hid, const float* __restrict__ rhid,
    const float* __restrict__ owT, const float* __restrict__ ob,
    const float* __restrict__ rb, float* __restrict__ out)
{
    extern __shared__ float sh[];
    const int tid = threadIdx.x;
    const int bt0 = blockIdx.x * 16;

    for (int i = tid; i < 16 * 512; i += 256) {
        int r = i >> 9, cc = i & 511;
        sh[r * 1024 + cc]       = hid[(size_t)(bt0 + r) * 512 + cc];
        sh[r * 1024 + 512 + cc] = rhid[(size_t)(bt0 + r) * 512 + cc];
    }
    __syncthreads();

    #pragma unroll
    for (int p0 = 0; p0 < 16 * 96; p0 += 256) {
        int p = p0 + tid;
        int row = p / 96, o = p % 96;
        const float* base = sh + row * 1024 + ((o < 3) ? 0 : 512);
        float acc = 0.f;
        #pragma unroll 8
        for (int h = 0; h < 512; ++h)
            acc = fmaf(__ldg(owT + h * 96 + o), base[h], acc);
        int bt = bt0 + row;
        if (o < 3) out[(size_t)bt * 3 + o] = acc + ob[o];
        else       out[(size_t)BTROWS * 3 + (size_t)bt * 93 + (o - 3)] = acc + rb[o - 3];
    }
}

// ---------------- launch ------------------------------------------------------
extern "C" void kernel_launch(void* const* d_in, const int* in_sizes, int n_in,
                              void* d_out, int out_size)
{
    const int*   wid   = (const int*)d_in[0];
    const int*   pid   = (const int*)d_in[1];
    const int*   fidx  = (const int*)d_in[2];
    const float* wl    = (const float*)d_in[3];
    const float* pl    = (const float*)d_in[4];
    const float* Wih1f = (const float*)d_in[5];
    const float* Whh1f = (const float*)d_in[6];
    const float* bih1f = (const float*)d_in[7];
    const float* bhh1f = (const float*)d_in[8];
    const float* Wih1b = (const float*)d_in[9];
    const float* Whh1b = (const float*)d_in[10];
    const float* bih1b = (const float*)d_in[11];
    const float* bhh1b = (const float*)d_in[12];
    const float* Wih2f = (const float*)d_in[13];
    const float* Whh2f = (const float*)d_in[14];
    const float* bih2f = (const float*)d_in[15];
    const float* bhh2f = (const float*)d_in[16];
    const float* Wih2b = (const float*)d_in[17];
    const float* Whh2b = (const float*)d_in[18];
    const float* bih2b = (const float*)d_in[19];
    const float* bhh2b = (const float*)d_in[20];
    const float* hidL  = (const float*)d_in[21];
    const float* hidB  = (const float*)d_in[22];
    const float* outL  = (const float*)d_in[23];
    const float* outB  = (const float*)d_in[24];
    const float* rhidL = (const float*)d_in[25];
    const float* rhidB = (const float*)d_in[26];
    const float* routL = (const float*)d_in[27];
    const float* routB = (const float*)d_in[28];
    float* out = (float*)d_out;

    float* scr = nullptr;
    cudaGetSymbolAddress((void**)&scr, g_f32);
    __nv_bfloat16* bfp = nullptr;
    cudaGetSymbolAddress((void**)&bfp, g_bf);

    float* xgf  = scr + O_XGF;
    float* xgb  = scr + O_XGB;
    float* hid  = scr + O_HID;
    float* rhid = scr + O_RHID;
    float* whht = scr + O_WHHT;
    float* hTf  = scr + O_HTF;
    float* hTb  = scr + O_HTB;
    float* owT  = scr + O_OWT;
    float* bs1  = scr + O_BS1;
    float* bs2  = scr + O_BS2;
    float* bsm  = scr + O_BSM;

    __nv_bfloat16* ivhi = bfp + B_IVHI;
    __nv_bfloat16* ivlo = bfp + B_IVLO;
    __nv_bfloat16* avhi = bfp + B_AVHI;
    __nv_bfloat16* avlo = bfp + B_AVLO;
    __nv_bfloat16* v2hi = bfp + B_V2HI;
    __nv_bfloat16* v2lo = bfp + B_V2LO;
    __nv_bfloat16* w1hi = bfp + B_W1HI;
    __nv_bfloat16* w1lo = bfp + B_W1LO;
    __nv_bfloat16* w2hi = bfp + B_W2HI;
    __nv_bfloat16* w2lo = bfp + B_W2LO;
    __nv_bfloat16* wmhi = bfp + B_WMHI;
    __nv_bfloat16* wmlo = bfp + B_WMLO;

    cudaFuncSetAttribute(k_recur, cudaFuncAttributeMaxDynamicSharedMemorySize, 98304);
    cudaFuncSetAttribute(k_hmma<false, false>, cudaFuncAttributeMaxDynamicSharedMemorySize, NST * STG);
    cudaFuncSetAttribute(k_hmma<true, true>,  cudaFuncAttributeMaxDynamicSharedMemorySize, NST * STG);
    cudaFuncSetAttribute(k_out2, cudaFuncAttributeMaxDynamicSharedMemorySize, 65536);

    dim3 gx(16, 128);
    // 0: embeddings
    k_embed_split<<<(MROWS * 192 + 255) / 256, 256>>>(wid, pid, wl, pl, ivhi, ivlo);
    // 1: layer-1 input weights split
    k_wsplit<<<(2048 * 192 + 255) / 256, 256>>>(Wih1f, Wih1b, 1024, 160, 192, w1hi, w1lo, 2048 * 192);
    // 2: layer-1 bias
    k_bias2<<<8, 256>>>(bih1f, bhh1f, bih1b, bhh1b, bs1);
    // 3: xg GEMM layer 1   <-- ncu capture lands here
    k_hmma<false, false><<<gx, 256, NST * STG>>>(ivhi, ivlo, w1hi, w1lo, bs1, xgf, xgb, 1024, 192, nullptr);
    // 4: Whh transposes + zero hT + zero flags
    k_whht_all<<<4096, 256>>>(Whh1f, Whh1b, Whh2f, Whh2b, whht, hTf, hTb);
    // 5: recurrence layer 1
    k_recur<<<128, 256, 98304>>>(xgf, xgb, whht + 0 * SZ_WHHT, whht + 1 * SZ_WHHT, avhi, avlo, hTf, hTb);
    // 6-8: layer 2
    k_wsplit<<<(2048 * 512 + 255) / 256, 256>>>(Wih2f, Wih2b, 1024, 512, 512, w2hi, w2lo, 2048 * 512);
    k_bias2<<<8, 256>>>(bih2f, bhh2f, bih2b, bhh2b, bs2);
    k_hmma<false, false><<<gx, 256, NST * STG>>>(avhi, avlo, w2hi, w2lo, bs2, xgf, xgb, 1024, 512, nullptr);
    // 9-10: reset + recurrence layer 2
    k_reset2<<<256, 256>>>(hTf, hTb);
    k_recur<<<128, 256, 98304>>>(xgf, xgb, whht + 2 * SZ_WHHT, whht + 3 * SZ_WHHT, v2hi, v2lo, hTf, hTb);
    // 11-13: MLP head prep
    k_wsplit<<<(1024 * 6144 + 255) / 256, 256>>>(hidL, rhidL, 512, 6144, 6144, wmhi, wmlo, 1024 * 6144);
    k_bcat<<<4, 256>>>(hidB, rhidB, bsm);
    k_owt<<<(512 * 96 + 255) / 256, 256>>>(outL, routL, owT);
    // 14: MLP head GEMM (gathered, hid|rhid fused, tanh epilogue)
    dim3 gm(8, 128);
    k_hmma<true, true><<<gm, 256, NST * STG>>>(v2hi, v2lo, wmhi, wmlo, bsm, hid, rhid, 512, 6144, fidx);
    // 15: tiled output head
    k_out2<<<BTROWS / 16, 256, 65536>>>(hid, rhid, owT, outB, routB, out);
}

// round 17
// speedup vs baseline: 1.0611x; 1.0181x over previous
#include <cuda_runtime.h>
#include <cuda_bf16.h>
#include <math.h>
#include <stdint.h>

// ---------------- problem constants ----------------
#define BBATCH 64
#define SSEQ   256
#define HHID   256
#define MROWS  16384
#define BTROWS 16384

// ---------------- fp32 scratch ----------------
#define O_XGF   ((size_t)0)
#define SZ_XG   ((size_t)MROWS*1024)
#define O_XGB   (O_XGF+SZ_XG)
#define O_HID   (O_XGB+SZ_XG)
#define SZ_HID  ((size_t)BTROWS*512)
#define O_RHID  (O_HID+SZ_HID)
#define O_WHHT  (O_RHID+SZ_HID)
#define SZ_WHHT ((size_t)HHID*HHID*4)
#define O_HTF   (O_WHHT+4*SZ_WHHT)
#define SZ_HT   ((size_t)2*HHID*BBATCH)
#define O_HTB   (O_HTF+SZ_HT)
#define O_OWT   (O_HTB+SZ_HT)
#define SZ_OWT  ((size_t)512*96)
#define O_BS1   (O_OWT+SZ_OWT)
#define O_BS2   (O_BS1+2048)
#define O_BSM   (O_BS2+2048)
#define F32_TOTAL (O_BSM+1024)

__device__ float g_f32[F32_TOTAL];

// ---------------- bf16 scratch ----------------
#define B_IVHI ((size_t)0)
#define SZ_IV  ((size_t)MROWS*192)
#define B_IVLO (B_IVHI+SZ_IV)
#define B_AVHI (B_IVLO+SZ_IV)
#define SZ_AV  ((size_t)MROWS*512)
#define B_AVLO (B_AVHI+SZ_AV)
#define B_V2HI (B_AVLO+SZ_AV)
#define B_V2LO (B_V2HI+SZ_AV)
#define B_W1HI (B_V2LO+SZ_AV)
#define SZ_W1  ((size_t)2048*192)
#define B_W1LO (B_W1HI+SZ_W1)
#define B_W2HI (B_W1LO+SZ_W1)
#define SZ_W2  ((size_t)2048*512)
#define B_W2LO (B_W2HI+SZ_W2)
#define B_WMHI (B_W2LO+SZ_W2)
#define SZ_WM  ((size_t)1024*6144)
#define B_WMLO (B_WMHI+SZ_WM)
#define BF_TOTAL (B_WMLO+SZ_WM)

__device__ __nv_bfloat16 g_bf[BF_TOTAL];

// per-direction, per-b-group (4), per-jh-block (16) flags: one per 128B line
#define FLAG_STRIDE 32
__device__ unsigned g_flags[2][4][16][FLAG_STRIDE];
#define NFLAGWORDS (2 * 4 * 16 * FLAG_STRIDE)

// ---------------- packed f32x2 helpers (Blackwell) ----------------
__device__ __forceinline__ unsigned long long pack2(float lo, float hi) {
    unsigned long long r;
    asm("mov.b64 %0, {%1, %2};" : "=l"(r) : "f"(lo), "f"(hi));
    return r;
}
__device__ __forceinline__ void unpack2(unsigned long long p, float& lo, float& hi) {
    asm("mov.b64 {%0, %1}, %2;" : "=f"(lo), "=f"(hi) : "l"(p));
}
#define FMA2(acc, a, b) \
    asm("fma.rn.f32x2 %0, %1, %2, %0;" : "+l"(acc) : "l"(a), "l"(b))
#define ADD2(acc, a) \
    asm("add.rn.f32x2 %0, %0, %1;" : "+l"(acc) : "l"(a))

// ---------------- small prep kernels (unchanged, R9-proven) ----------------
__global__ void k_embed_split(const int* __restrict__ wid, const int* __restrict__ pid,
                              const float* __restrict__ wl, const float* __restrict__ pl,
                              __nv_bfloat16* __restrict__ hi, __nv_bfloat16* __restrict__ lo)
{
    int i = blockIdx.x * 256 + threadIdx.x;
    if (i >= MROWS * 192) return;
    int col = i % 192, bs = i / 192;
    float v = 0.f;
    if (col < 128)      v = wl[(size_t)wid[bs] * 128 + col];
    else if (col < 160) v = pl[(size_t)pid[bs] * 32 + (col - 128)];
    __nv_bfloat16 h = __float2bfloat16(v);
    hi[i] = h;
    lo[i] = __float2bfloat16(v - __bfloat162float(h));
}

__global__ void k_wsplit(const float* __restrict__ W0, const float* __restrict__ W1,
                         int N0, int Ksrc, int Kpad,
                         __nv_bfloat16* __restrict__ hi, __nv_bfloat16* __restrict__ lo, int total)
{
    int i = blockIdx.x * 256 + threadIdx.x;
    if (i >= total) return;
    int row = i / Kpad, col = i % Kpad;
    float v = 0.f;
    if (col < Ksrc)
        v = (row < N0) ? W0[(size_t)row * Ksrc + col]
                       : W1[(size_t)(row - N0) * Ksrc + col];
    __nv_bfloat16 h = __float2bfloat16(v);
    hi[i] = h;
    lo[i] = __float2bfloat16(v - __bfloat162float(h));
}

__global__ void k_bias2(const float* a, const float* b, const float* c, const float* d,
                        float* __restrict__ o)
{
    int i = blockIdx.x * 256 + threadIdx.x;
    if (i >= 2048) return;
    o[i] = (i < 1024) ? a[i] + b[i] : c[i - 1024] + d[i - 1024];
}

__global__ void k_bcat(const float* a, const float* b, float* __restrict__ o)
{
    int i = blockIdx.x * 256 + threadIdx.x;
    if (i >= 1024) return;
    o[i] = (i < 512) ? a[i] : b[i - 512];
}

__global__ void k_whht_all(const float* __restrict__ w0, const float* __restrict__ w1,
                           const float* __restrict__ w2, const float* __restrict__ w3,
                           float* __restrict__ o, float* __restrict__ hTf, float* __restrict__ hTb)
{
    int i = blockIdx.x * 256 + threadIdx.x;
    if (i < 4 * 262144) {
        int which = i >> 18, local = i & 262143;
        int k = local >> 10, rem = local & 1023, jh = rem >> 2, g = rem & 3;
        const float* w = (which == 0) ? w0 : (which == 1) ? w1 : (which == 2) ? w2 : w3;
        o[i] = w[((g << 8) + jh) * HHID + k];
    }
    if (i < 2 * (int)SZ_HT) {
        if (i < (int)SZ_HT) hTf[i] = 0.f;
        else                hTb[i - SZ_HT] = 0.f;
    }
    if (i < NFLAGWORDS) ((unsigned*)g_flags)[i] = 0u;
}

__global__ void k_owt(const float* __restrict__ outL, const float* __restrict__ routL,
                      float* __restrict__ owT)
{
    int i = blockIdx.x * 256 + threadIdx.x;
    if (i >= 512 * 96) return;
    int h = i / 96, o = i % 96;
    owT[i] = (o < 3) ? outL[o * 512 + h] : routL[(o - 3) * 512 + h];
}

__global__ void k_reset2(float* __restrict__ hTf, float* __restrict__ hTb)
{
    int i = blockIdx.x * 256 + threadIdx.x;
    if (i < 2 * (int)SZ_HT) {
        if (i < (int)SZ_HT) hTf[i] = 0.f;
        else                hTb[i - SZ_HT] = 0.f;
    }
    if (i < NFLAGWORDS) ((unsigned*)g_flags)[i] = 0u;
}

// ---------------- fast activations ----------------
__device__ __forceinline__ float fsigmoid(float x) {
    return __fdividef(1.f, 1.f + __expf(-x));
}
__device__ __forceinline__ float ftanh(float x) {
    float t = __expf(-2.f * x);
    return __fdividef(1.f - t, 1.f + t);
}

// ---------------- persistent biLSTM recurrence -------------------------------
// k-split across warps; h in registers; packed fma.rn.f32x2 gate math;
// fast activations; b-group barrier.
__global__ void __launch_bounds__(256, 1) k_recur(
    const float* __restrict__ xgf, const float* __restrict__ xgb,
    const float* __restrict__ wtf, const float* __restrict__ wtb,
    __nv_bfloat16* __restrict__ vhi, __nv_bfloat16* __restrict__ vlo,
    float* __restrict__ hTf, float* __restrict__ hTb)
{
    extern __shared__ float sm[];
    float* sh_w    = sm;            // [256 k][16 jh][4 gates]  (64 KB)
    float* sh_part = sm + 16384;    // [8 warp][256 cell][4 gates] (32 KB)

    const int tid  = threadIdx.x;
    const int wid  = tid >> 5;
    const int lane = tid & 31;
    const int dir  = blockIdx.x >> 6;
    const int sub  = blockIdx.x & 63;
    const int b0i  = sub & 3;
    const int jh0i = sub >> 2;
    const int b0   = b0i * 16;
    const int jh0  = jh0i * 16;
    const int bl   = tid >> 4, jhl = tid & 15;
    const int b    = b0 + bl,  jh  = jh0 + jhl;
    const int bl2  = lane & 15;
    const int hf   = lane >> 4;

    const float* xg = dir ? xgb : xgf;
    const float* wt = dir ? wtb : wtf;
    float*       hT = dir ? hTb : hTf;

    for (int idx = tid; idx < 16384; idx += 256) {
        int k = idx >> 6, r = idx & 63;
        sh_w[idx] = wt[k * 1024 + jh0 * 4 + r];
    }

    float c = 0.f;
    __syncthreads();

    int s0 = dir ? (SSEQ - 1) : 0;
    const float* xr0 = xg + ((size_t)(b * SSEQ + s0)) * 1024 + jh;
    float ai = __ldg(xr0 +   0);
    float af = __ldg(xr0 + 256);
    float ag = __ldg(xr0 + 512);
    float ao = __ldg(xr0 + 768);

    unsigned* myflag   = &g_flags[dir][b0i][jh0i][0];
    unsigned* pollflag = &g_flags[dir][b0i][tid & 15][0];

    const int k0w = wid * 32;

    for (int it = 0; it < SSEQ; ++it) {
        const float* hcur = hT + (it & 1) * (HHID * BBATCH);
        float*       hnxt = hT + ((it & 1) ^ 1) * (HHID * BBATCH);

        float hreg[32];
        #pragma unroll
        for (int kk = 0; kk < 32; ++kk)
            hreg[kk] = __ldcg(hcur + (k0w + kk) * 64 + b0 + bl2);

        // packed accumulators: [j][0]=(i,f) [j][1]=(g,o)
        unsigned long long acc[8][2];
        #pragma unroll
        for (int j = 0; j < 8; ++j) { acc[j][0] = 0ull; acc[j][1] = 0ull; }

        #pragma unroll 2
        for (int kk = 0; kk < 32; ++kk) {
            int k = k0w + kk;
            unsigned long long hp = pack2(hreg[kk], hreg[kk]);
            const ulonglong2* wr = (const ulonglong2*)(sh_w + k * 64 + hf * 32);
            #pragma unroll
            for (int j = 0; j < 8; ++j) {
                ulonglong2 wv = wr[j];
                FMA2(acc[j][0], hp, wv.x);
                FMA2(acc[j][1], hp, wv.y);
            }
        }

        #pragma unroll
        for (int j = 0; j < 8; ++j) {
            int cell = bl2 * 16 + hf * 8 + j;
            *(ulonglong2*)(sh_part + wid * 1024 + cell * 4) =
                make_ulonglong2(acc[j][0], acc[j][1]);
        }
        __syncthreads();

        unsigned long long s01 = pack2(ai, af);
        unsigned long long s23 = pack2(ag, ao);
        #pragma unroll
        for (int w = 0; w < 8; ++w) {
            ulonglong2 p = *(const ulonglong2*)(sh_part + w * 1024 + tid * 4);
            ADD2(s01, p.x);
            ADD2(s23, p.y);
        }
        float si, sf, sg, so;
        unpack2(s01, si, sf);
        unpack2(s23, sg, so);

        const int s = dir ? (SSEQ - 1 - it) : it;
        float ig = fsigmoid(si);
        float fg = fsigmoid(sf);
        float gv = ftanh(sg);
        float og = fsigmoid(so);
        c = fmaf(fg, c, ig * gv);
        float h = og * ftanh(c);

        __stcg(hnxt + jh * 64 + b, h);

        // arrival (release)
        __threadfence();
        __syncthreads();
        unsigned epoch = (unsigned)(it + 1);
        if (tid == 0) {
            asm volatile("st.relaxed.gpu.global.u32 [%0], %1;"
                         :: "l"(myflag), "r"(epoch) : "memory");
        }

        // overlapped epilogue
        size_t off = ((size_t)(b * SSEQ + s)) * 512 + (dir << 8) + jh;
        __nv_bfloat16 hh = __float2bfloat16(h);
        vhi[off] = hh;
        vlo[off] = __float2bfloat16(h - __bfloat162float(hh));
        if (it + 1 < SSEQ) {
            const int sn = dir ? (SSEQ - 2 - it) : (it + 1);
            const float* xrn = xg + ((size_t)(b * SSEQ + sn)) * 1024 + jh;
            ai = __ldg(xrn +   0);
            af = __ldg(xrn + 256);
            ag = __ldg(xrn + 512);
            ao = __ldg(xrn + 768);
        }

        // wait (acquire): 16 same-b0 blocks
        if (tid < 16) {
            unsigned v;
            do {
                asm volatile("ld.relaxed.gpu.global.u32 %0, [%1];"
                             : "=r"(v) : "l"(pollflag) : "memory");
            } while (v < epoch);
            __threadfence();
        }
        __syncthreads();
    }
}

// ---------------- HMMA bf16 3-product split GEMM, double-buffered, 2 CTA/SM --
#define KC    32
#define TROWB 80
#define TILE2 10240
#define STG   40960
#define NST   2

__device__ __forceinline__ uint32_t smem_u32(const void* p) {
    uint32_t a;
    asm("{ .reg .u64 t; cvta.to.shared.u64 t, %1; cvt.u32.u64 %0, t; }"
        : "=r"(a) : "l"(p));
    return a;
}
__device__ __forceinline__ void cpasync16(uint32_t dst, const void* src) {
    asm volatile("cp.async.ca.shared.global [%0], [%1], 16;" :: "r"(dst), "l"(src));
}
#define CP_COMMIT() asm volatile("cp.async.commit_group;" ::: "memory")
#define CP_WAIT1()  asm volatile("cp.async.wait_group 1;" ::: "memory")
#define CP_WAIT0()  asm volatile("cp.async.wait_group 0;" ::: "memory")

__device__ __forceinline__ void ldsm4(uint32_t addr, uint32_t* r) {
    asm volatile("ldmatrix.sync.aligned.m8n8.x4.shared.b16 {%0,%1,%2,%3}, [%4];"
        : "=r"(r[0]), "=r"(r[1]), "=r"(r[2]), "=r"(r[3]) : "r"(addr));
}

__device__ __forceinline__ void mma16816(float* d, const uint32_t* a, const uint32_t* b) {
    asm volatile(
        "mma.sync.aligned.m16n8k16.row.col.f32.bf16.bf16.f32 "
        "{%0,%1,%2,%3}, {%4,%5,%6,%7}, {%8,%9}, {%0,%1,%2,%3};"
        : "+f"(d[0]), "+f"(d[1]), "+f"(d[2]), "+f"(d[3])
        : "r"(a[0]), "r"(a[1]), "r"(a[2]), "r"(a[3]), "r"(b[0]), "r"(b[1]));
}

template<bool GATHER>
__device__ __forceinline__ void issue_stage(
    uint32_t sbase, int stage, int c, int row0, int n0, int KU,
    const uint4* A4h, const uint4* A4l, const uint4* W4h, const uint4* W4l,
    const int* fidx, int tid)
{
    const int k0 = c * KC;
    const uint32_t dstb = sbase + stage * STG;
    #pragma unroll
    for (int u0 = 0; u0 < 2048; u0 += 256) {
        int u = u0 + tid;
        int tile = u >> 9;
        int v = u & 511;
        int r = v >> 2, j = v & 3;
        const uint4* src;
        if (tile < 2) {
            const uint4* base = tile ? A4l : A4h;
            if (GATHER) {
                int m    = row0 + r;
                int slot = k0 >> 9;
                int fi   = __ldg(fidx + m * 12 + slot);
                int srow = ((m >> 8) << 8) + fi;
                src = base + (size_t)srow * 64 + ((k0 & 511) >> 3) + j;
            } else {
                src = base + (size_t)(row0 + r) * KU + (k0 >> 3) + j;
            }
        } else {
            const uint4* base = (tile == 3) ? W4l : W4h;
            src = base + (size_t)(n0 + r) * KU + (k0 >> 3) + j;
        }
        cpasync16(dstb + tile * TILE2 + r * TROWB + j * 16, src);
    }
    CP_COMMIT();
}

template<bool GATHER, bool TANH>
__global__ void __launch_bounds__(256, 2) k_hmma(
    const __nv_bfloat16* __restrict__ Ahi, const __nv_bfloat16* __restrict__ Alo,
    const __nv_bfloat16* __restrict__ Whi, const __nv_bfloat16* __restrict__ Wlo,
    const float* __restrict__ bias, float* __restrict__ C0, float* __restrict__ C1,
    int halfN, int Kpad, const int* __restrict__ fidx)
{
    extern __shared__ __align__(16) char smem[];
    const uint32_t sb = smem_u32(smem);
    const int tid  = threadIdx.x;
    const int wid  = tid >> 5;
    const int lane = tid & 31;
    const int grp  = lane >> 2;
    const int quad = lane & 3;
    const int row0 = blockIdx.y * 128;
    const int n0   = blockIdx.x * 128;
    const int wm   = (wid & 3) * 32;
    const int wn   = (wid >> 2) * 64;

    const int lg = lane >> 3;
    const uint32_t aoff = ((lane & 7) + ((lg & 1) << 3)) * TROWB + ((lg >> 1) << 4);
    const uint32_t boff = ((lane & 7) + ((lg >> 1) << 3)) * TROWB + ((lg & 1) << 4);

    const int KU = Kpad >> 3;
    const uint4* A4h = (const uint4*)Ahi;
    const uint4* A4l = (const uint4*)Alo;
    const uint4* W4h = (const uint4*)Whi;
    const uint4* W4l = (const uint4*)Wlo;

    float acc[2][8][4];
    #pragma unroll
    for (int i = 0; i < 2; ++i)
        #pragma unroll
        for (int j = 0; j < 8; ++j)
            #pragma unroll
            for (int q = 0; q < 4; ++q) acc[i][j][q] = 0.f;

    const int nch = Kpad / KC;
    issue_stage<GATHER>(sb, 0, 0, row0, n0, KU, A4h, A4l, W4h, W4l, fidx, tid);

    for (int c = 0; c < nch; ++c) {
        __syncthreads();
        if (c + 1 < nch) {
            issue_stage<GATHER>(sb, (c + 1) & 1, c + 1, row0, n0, KU,
                                A4h, A4l, W4h, W4l, fidx, tid);
            CP_WAIT1();
        } else {
            CP_WAIT0();
        }
        __syncthreads();

        const uint32_t bufa = sb + (c & 1) * STG;
        #pragma unroll
        for (int ks = 0; ks < 2; ++ks) {
            uint32_t ah[8], al[8];
            #pragma unroll
            for (int mt = 0; mt < 2; ++mt) {
                uint32_t addr = bufa + (uint32_t)(wm + mt * 16) * TROWB + ks * 32 + aoff;
                ldsm4(addr,          ah + mt * 4);
                ldsm4(addr + TILE2,  al + mt * 4);
            }
            #pragma unroll
            for (int np = 0; np < 4; ++np) {
                uint32_t bh[4], bl[4];
                uint32_t addr = bufa + 2 * TILE2 + (uint32_t)(wn + np * 16) * TROWB + ks * 32 + boff;
                ldsm4(addr,          bh);
                ldsm4(addr + TILE2,  bl);
                #pragma unroll
                for (int mt = 0; mt < 2; ++mt)
                    #pragma unroll
                    for (int nh = 0; nh < 2; ++nh) {
                        int nt = np * 2 + nh;
                        mma16816(acc[mt][nt], ah + mt * 4, bh + nh * 2);
                        mma16816(acc[mt][nt], ah + mt * 4, bl + nh * 2);
                        mma16816(acc[mt][nt], al + mt * 4, bh + nh * 2);
                    }
            }
        }
    }

    const int gbase = n0 + wn;
    float* Co;
    int cbase;
    if (gbase < halfN) { Co = C0; cbase = gbase; }
    else               { Co = C1; cbase = gbase - halfN; }

    #pragma unroll
    for (int mt = 0; mt < 2; ++mt) {
        int r = row0 + wm + mt * 16 + grp;
        #pragma unroll
        for (int nt = 0; nt < 8; ++nt) {
            int gc = gbase + nt * 8 + quad * 2;
            float b0v = bias[gc], b1v = bias[gc + 1];
            float v0 = acc[mt][nt][0] + b0v;
            float v1 = acc[mt][nt][1] + b1v;
            float v2 = acc[mt][nt][2] + b0v;
            float v3 = acc[mt][nt][3] + b1v;
            if (TANH) { v0 = tanhf(v0); v1 = tanhf(v1); v2 = tanhf(v2); v3 = tanhf(v3); }
            int cc = cbase + nt * 8 + quad * 2;
            *(float2*)(Co + (size_t)r * halfN + cc)       = make_float2(v0, v1);
            *(float2*)(Co + (size_t)(r + 8) * halfN + cc) = make_float2(v2, v3);
        }
    }
}

// ---------------- tiled output head: 16 bt rows per block --------------------
__global__ void __launch_bounds__(256) k_out2(
    const float* __restrict__ hid, const float* __restrict__ rhid,
    const float* __restrict__ owT, const float* __restrict__ ob,
    const float* __restrict__ rb, float* __restrict__ out)
{
    extern __shared__ float sh[];
    const int tid = threadIdx.x;
    const int bt0 = blockIdx.x * 16;

    for (int i = tid; i < 16 * 512; i += 256) {
        int r = i >> 9, cc = i & 511;
        sh[r * 1024 + cc]       = hid[(size_t)(bt0 + r) * 512 + cc];
        sh[r * 1024 + 512 + cc] = rhid[(size_t)(bt0 + r) * 512 + cc];
    }
    __syncthreads();

    #pragma unroll
    for (int p0 = 0; p0 < 16 * 96; p0 += 256) {
        int p = p0 + tid;
        int row = p / 96, o = p % 96;
        const float* base = sh + row * 1024 + ((o < 3) ? 0 : 512);
        float acc = 0.f;
        #pragma unroll 8
        for (int h = 0; h < 512; ++h)
            acc = fmaf(__ldg(owT + h * 96 + o), base[h], acc);
        int bt = bt0 + row;
        if (o < 3) out[(size_t)bt * 3 + o] = acc + ob[o];
        else       out[(size_t)BTROWS * 3 + (size_t)bt * 93 + (o - 3)] = acc + rb[o - 3];
    }
}

// ---------------- launch ------------------------------------------------------
extern "C" void kernel_launch(void* const* d_in, const int* in_sizes, int n_in,
                              void* d_out, int out_size)
{
    const int*   wid   = (const int*)d_in[0];
    const int*   pid   = (const int*)d_in[1];
    const int*   fidx  = (const int*)d_in[2];
    const float* wl    = (const float*)d_in[3];
    const float* pl    = (const float*)d_in[4];
    const float* Wih1f = (const float*)d_in[5];
    const float* Whh1f = (const float*)d_in[6];
    const float* bih1f = (const float*)d_in[7];
    const float* bhh1f = (const float*)d_in[8];
    const float* Wih1b = (const float*)d_in[9];
    const float* Whh1b = (const float*)d_in[10];
    const float* bih1b = (const float*)d_in[11];
    const float* bhh1b = (const float*)d_in[12];
    const float* Wih2f = (const float*)d_in[13];
    const float* Whh2f = (const float*)d_in[14];
    const float* bih2f = (const float*)d_in[15];
    const float* bhh2f = (const float*)d_in[16];
    const float* Wih2b = (const float*)d_in[17];
    const float* Whh2b = (const float*)d_in[18];
    const float* bih2b = (const float*)d_in[19];
    const float* bhh2b = (const float*)d_in[20];
    const float* hidL  = (const float*)d_in[21];
    const float* hidB  = (const float*)d_in[22];
    const float* outL  = (const float*)d_in[23];
    const float* outB  = (const float*)d_in[24];
    const float* rhidL = (const float*)d_in[25];
    const float* rhidB = (const float*)d_in[26];
    const float* routL = (const float*)d_in[27];
    const float* routB = (const float*)d_in[28];
    float* out = (float*)d_out;

    float* scr = nullptr;
    cudaGetSymbolAddress((void**)&scr, g_f32);
    __nv_bfloat16* bfp = nullptr;
    cudaGetSymbolAddress((void**)&bfp, g_bf);

    float* xgf  = scr + O_XGF;
    float* xgb  = scr + O_XGB;
    float* hid  = scr + O_HID;
    float* rhid = scr + O_RHID;
    float* whht = scr + O_WHHT;
    float* hTf  = scr + O_HTF;
    float* hTb  = scr + O_HTB;
    float* owT  = scr + O_OWT;
    float* bs1  = scr + O_BS1;
    float* bs2  = scr + O_BS2;
    float* bsm  = scr + O_BSM;

    __nv_bfloat16* ivhi = bfp + B_IVHI;
    __nv_bfloat16* ivlo = bfp + B_IVLO;
    __nv_bfloat16* avhi = bfp + B_AVHI;
    __nv_bfloat16* avlo = bfp + B_AVLO;
    __nv_bfloat16* v2hi = bfp + B_V2HI;
    __nv_bfloat16* v2lo = bfp + B_V2LO;
    __nv_bfloat16* w1hi = bfp + B_W1HI;
    __nv_bfloat16* w1lo = bfp + B_W1LO;
    __nv_bfloat16* w2hi = bfp + B_W2HI;
    __nv_bfloat16* w2lo = bfp + B_W2LO;
    __nv_bfloat16* wmhi = bfp + B_WMHI;
    __nv_bfloat16* wmlo = bfp + B_WMLO;

    cudaFuncSetAttribute(k_recur, cudaFuncAttributeMaxDynamicSharedMemorySize, 98304);
    cudaFuncSetAttribute(k_hmma<false, false>, cudaFuncAttributeMaxDynamicSharedMemorySize, NST * STG);
    cudaFuncSetAttribute(k_hmma<true, true>,  cudaFuncAttributeMaxDynamicSharedMemorySize, NST * STG);
    cudaFuncSetAttribute(k_out2, cudaFuncAttributeMaxDynamicSharedMemorySize, 65536);

    dim3 gx(16, 128);
    // 0: embeddings
    k_embed_split<<<(MROWS * 192 + 255) / 256, 256>>>(wid, pid, wl, pl, ivhi, ivlo);
    // 1: layer-1 input weights split
    k_wsplit<<<(2048 * 192 + 255) / 256, 256>>>(Wih1f, Wih1b, 1024, 160, 192, w1hi, w1lo, 2048 * 192);
    // 2: layer-1 bias
    k_bias2<<<8, 256>>>(bih1f, bhh1f, bih1b, bhh1b, bs1);
    // 3: xg GEMM layer 1   <-- ncu capture lands here
    k_hmma<false, false><<<gx, 256, NST * STG>>>(ivhi, ivlo, w1hi, w1lo, bs1, xgf, xgb, 1024, 192, nullptr);
    // 4: Whh transposes + zero hT + zero flags
    k_whht_all<<<4096, 256>>>(Whh1f, Whh1b, Whh2f, Whh2b, whht, hTf, hTb);
    // 5: recurrence layer 1
    k_recur<<<128, 256, 98304>>>(xgf, xgb, whht + 0 * SZ_WHHT, whht + 1 * SZ_WHHT, avhi, avlo, hTf, hTb);
    // 6-8: layer 2
    k_wsplit<<<(2048 * 512 + 255) / 256, 256>>>(Wih2f, Wih2b, 1024, 512, 512, w2hi, w2lo, 2048 * 512);
    k_bias2<<<8, 256>>>(bih2f, bhh2f, bih2b, bhh2b, bs2);
    k_hmma<false, false><<<gx, 256, NST * STG>>>(avhi, avlo, w2hi, w2lo, bs2, xgf, xgb, 1024, 512, nullptr);
    // 9-10: reset + recurrence layer 2
    k_reset2<<<256, 256>>>(hTf, hTb);
    k_recur<<<128, 256, 98304>>>(xgf, xgb, whht + 2 * SZ_WHHT, whht + 3 * SZ_WHHT, v2hi, v2lo, hTf, hTb);
    // 11-13: MLP head prep
    k_wsplit<<<(1024 * 6144 + 255) / 256, 256>>>(hidL, rhidL, 512, 6144, 6144, wmhi, wmlo, 1024 * 6144);
    k_bcat<<<4, 256>>>(hidB, rhidB, bsm);
    k_owt<<<(512 * 96 + 255) / 256, 256>>>(outL, routL, owT);
    // 14: MLP head GEMM (gathered, hid|rhid fused, tanh epilogue)
    dim3 gm(8, 128);
    k_hmma<true, true><<<gm, 256, NST * STG>>>(v2hi, v2lo, wmhi, wmlo, bsm, hid, rhid, 512, 6144, fidx);
    // 15: tiled output head
    k_out2<<<BTROWS / 16, 256, 65536>>>(hid, rhid, owT, outB, routB, out);
}